// round 3
// baseline (speedup 1.0000x reference)
#include <cuda_runtime.h>

// ---------------------------------------------------------------------------
// StandGCN2: 2-layer GCN. N<=100096 nodes, F=128 -> 128 -> 64.
//   dinv = rsqrt(1 + indeg)
//   hs1  = dinv[r] * (x @ W1)           (self-loop seeds agg1)
//   agg1[d] += hs1[s]  over edges       (vector float4 atomics)
//   h1   = relu(dinv[r]*agg1 + b1)      (fused into GEMM2 A-load)
//   hs2  = dinv[r] * (h1 @ W2)          (seeds d_out)
//   d_out[d] += hs2[s] over edges
//   d_out = dinv[r]*d_out + b2
// ---------------------------------------------------------------------------

#define MAXN 100096

__device__ float g_deg[MAXN];
__device__ float g_dinv[MAXN];
__device__ __align__(16) float g_hs1[(size_t)MAXN * 128];
__device__ __align__(16) float g_agg1[(size_t)MAXN * 128];
__device__ __align__(16) float g_hs2[(size_t)MAXN * 64];

// ---------------------------------------------------------------------------
// Degree / normalization
// ---------------------------------------------------------------------------
__global__ void k_deg_init(int n) {
    int i = blockIdx.x * blockDim.x + threadIdx.x;
    if (i < n) g_deg[i] = 1.0f;  // self-loop
}

__global__ void k_deg_acc(const int* __restrict__ dst, int e) {
    int i = blockIdx.x * blockDim.x + threadIdx.x;
    if (i < e) atomicAdd(&g_deg[dst[i]], 1.0f);
}

__global__ void k_dinv(int n) {
    int i = blockIdx.x * blockDim.x + threadIdx.x;
    if (i < n) g_dinv[i] = rsqrtf(g_deg[i]);
}

// ---------------------------------------------------------------------------
// GEMM1: hs1 = agg1 = dinv[r] * (X @ W1),  X: [M,128], W1: [128,128]
// Block: 64 rows x 128 cols, 256 threads, thread tile 4x8, K chunked by 32.
// ---------------------------------------------------------------------------
__global__ __launch_bounds__(256) void k_gemm1(const float* __restrict__ X,
                                               const float* __restrict__ W,
                                               int M) {
    __shared__ float As[64][33];
    __shared__ float Bs[32][128];

    const int tid = threadIdx.x;
    const int row0 = blockIdx.x * 64;
    const int tx = tid & 15, ty = tid >> 4;
    const int r0 = ty * 4, c0 = tx * 8;

    float acc[4][8];
#pragma unroll
    for (int i = 0; i < 4; i++)
#pragma unroll
        for (int j = 0; j < 8; j++) acc[i][j] = 0.f;

    for (int kc = 0; kc < 4; kc++) {
        // A chunk: 64 rows x 32 k  (512 float4)
#pragma unroll
        for (int l = 0; l < 2; l++) {
            int i = tid + l * 256;
            int r = i >> 3, q = i & 7;
            int gr = row0 + r;
            float4 v = make_float4(0.f, 0.f, 0.f, 0.f);
            if (gr < M)
                v = reinterpret_cast<const float4*>(X)[(size_t)gr * 32 + kc * 8 + q];
            As[r][q * 4 + 0] = v.x;
            As[r][q * 4 + 1] = v.y;
            As[r][q * 4 + 2] = v.z;
            As[r][q * 4 + 3] = v.w;
        }
        // B chunk: 32 x 128  (1024 float4)
#pragma unroll
        for (int l = 0; l < 4; l++) {
            int i = tid + l * 256;
            reinterpret_cast<float4*>(&Bs[0][0])[i] =
                reinterpret_cast<const float4*>(W + (size_t)kc * 32 * 128)[i];
        }
        __syncthreads();

#pragma unroll
        for (int k = 0; k < 32; k++) {
            float a[4];
#pragma unroll
            for (int i = 0; i < 4; i++) a[i] = As[r0 + i][k];
            float4 bl = *reinterpret_cast<float4*>(&Bs[k][c0]);
            float4 bh = *reinterpret_cast<float4*>(&Bs[k][c0 + 4]);
            float b[8] = {bl.x, bl.y, bl.z, bl.w, bh.x, bh.y, bh.z, bh.w};
#pragma unroll
            for (int i = 0; i < 4; i++)
#pragma unroll
                for (int j = 0; j < 8; j++) acc[i][j] = fmaf(a[i], b[j], acc[i][j]);
        }
        __syncthreads();
    }

#pragma unroll
    for (int i = 0; i < 4; i++) {
        int gr = row0 + r0 + i;
        if (gr >= M) break;
        float dv = g_dinv[gr];
#pragma unroll
        for (int j = 0; j < 8; j += 4) {
            float4 v;
            v.x = acc[i][j + 0] * dv;
            v.y = acc[i][j + 1] * dv;
            v.z = acc[i][j + 2] * dv;
            v.w = acc[i][j + 3] * dv;
            *reinterpret_cast<float4*>(&g_hs1[(size_t)gr * 128 + c0 + j]) = v;
            *reinterpret_cast<float4*>(&g_agg1[(size_t)gr * 128 + c0 + j]) = v;
        }
    }
}

// ---------------------------------------------------------------------------
// Edge scatter 1: agg1[dst] += hs1[src].  One warp per edge (32 float4).
// ---------------------------------------------------------------------------
__global__ __launch_bounds__(256) void k_edge1(const int* __restrict__ src,
                                               const int* __restrict__ dst,
                                               int E) {
    int t = blockIdx.x * 256 + threadIdx.x;
    int e = t >> 5;
    if (e >= E) return;
    int j = t & 31;
    int s = src[e], d = dst[e];
    float4 v = *reinterpret_cast<const float4*>(&g_hs1[(size_t)s * 128 + j * 4]);
    atomicAdd(reinterpret_cast<float4*>(&g_agg1[(size_t)d * 128 + j * 4]), v);
}

// ---------------------------------------------------------------------------
// GEMM2: A[r][k] = relu(dinv[r]*agg1[r][k] + b1[k])  (fused on load)
//        hs2 = OUT = dinv[r] * (A @ W2),  W2: [128,64]
// Block: 64 rows x 64 cols, 256 threads, thread tile 4x4.
// ---------------------------------------------------------------------------
__global__ __launch_bounds__(256) void k_gemm2(const float* __restrict__ W2,
                                               const float* __restrict__ B1,
                                               float* __restrict__ OUT,
                                               int M) {
    __shared__ float As[64][33];
    __shared__ float Bs[32][64];

    const int tid = threadIdx.x;
    const int row0 = blockIdx.x * 64;
    const int tx = tid & 15, ty = tid >> 4;
    const int r0 = ty * 4, c0 = tx * 4;

    float acc[4][4];
#pragma unroll
    for (int i = 0; i < 4; i++)
#pragma unroll
        for (int j = 0; j < 4; j++) acc[i][j] = 0.f;

    for (int kc = 0; kc < 4; kc++) {
#pragma unroll
        for (int l = 0; l < 2; l++) {
            int i = tid + l * 256;
            int r = i >> 3, q = i & 7;
            int gr = row0 + r;
            float4 v = make_float4(0.f, 0.f, 0.f, 0.f);
            if (gr < M) {
                v = reinterpret_cast<const float4*>(g_agg1)[(size_t)gr * 32 + kc * 8 + q];
                float dv = g_dinv[gr];
                int kb = kc * 32 + q * 4;
                v.x = fmaxf(fmaf(dv, v.x, B1[kb + 0]), 0.f);
                v.y = fmaxf(fmaf(dv, v.y, B1[kb + 1]), 0.f);
                v.z = fmaxf(fmaf(dv, v.z, B1[kb + 2]), 0.f);
                v.w = fmaxf(fmaf(dv, v.w, B1[kb + 3]), 0.f);
            }
            As[r][q * 4 + 0] = v.x;
            As[r][q * 4 + 1] = v.y;
            As[r][q * 4 + 2] = v.z;
            As[r][q * 4 + 3] = v.w;
        }
        // B chunk: 32 x 64 (512 float4)
#pragma unroll
        for (int l = 0; l < 2; l++) {
            int i = tid + l * 256;
            reinterpret_cast<float4*>(&Bs[0][0])[i] =
                reinterpret_cast<const float4*>(W2 + (size_t)kc * 32 * 64)[i];
        }
        __syncthreads();

#pragma unroll
        for (int k = 0; k < 32; k++) {
            float a[4];
#pragma unroll
            for (int i = 0; i < 4; i++) a[i] = As[r0 + i][k];
            float4 b4 = *reinterpret_cast<float4*>(&Bs[k][c0]);
            float b[4] = {b4.x, b4.y, b4.z, b4.w};
#pragma unroll
            for (int i = 0; i < 4; i++)
#pragma unroll
                for (int j = 0; j < 4; j++) acc[i][j] = fmaf(a[i], b[j], acc[i][j]);
        }
        __syncthreads();
    }

#pragma unroll
    for (int i = 0; i < 4; i++) {
        int gr = row0 + r0 + i;
        if (gr >= M) break;
        float dv = g_dinv[gr];
        float4 v;
        v.x = acc[i][0] * dv;
        v.y = acc[i][1] * dv;
        v.z = acc[i][2] * dv;
        v.w = acc[i][3] * dv;
        *reinterpret_cast<float4*>(&g_hs2[(size_t)gr * 64 + c0]) = v;
        *reinterpret_cast<float4*>(&OUT[(size_t)gr * 64 + c0]) = v;
    }
}

// ---------------------------------------------------------------------------
// Edge scatter 2: OUT[dst] += hs2[src].  Half-warp per edge (16 float4).
// ---------------------------------------------------------------------------
__global__ __launch_bounds__(256) void k_edge2(const int* __restrict__ src,
                                               const int* __restrict__ dst,
                                               float* __restrict__ OUT,
                                               int E) {
    int t = blockIdx.x * 256 + threadIdx.x;
    int e = t >> 4;
    if (e >= E) return;
    int j = t & 15;
    int s = src[e], d = dst[e];
    float4 v = *reinterpret_cast<const float4*>(&g_hs2[(size_t)s * 64 + j * 4]);
    atomicAdd(reinterpret_cast<float4*>(&OUT[(size_t)d * 64 + j * 4]), v);
}

// ---------------------------------------------------------------------------
// Final: OUT = dinv[row]*OUT + b2
// ---------------------------------------------------------------------------
__global__ void k_final(float* __restrict__ OUT, const float* __restrict__ B2, int M) {
    int t = blockIdx.x * blockDim.x + threadIdx.x;
    if (t >= M * 16) return;
    int row = t >> 4, q = t & 15;
    float dv = g_dinv[row];
    float4 v = reinterpret_cast<float4*>(OUT)[t];
    float4 b = reinterpret_cast<const float4*>(B2)[q];
    v.x = fmaf(dv, v.x, b.x);
    v.y = fmaf(dv, v.y, b.y);
    v.z = fmaf(dv, v.z, b.z);
    v.w = fmaf(dv, v.w, b.w);
    reinterpret_cast<float4*>(OUT)[t] = v;
}

// ---------------------------------------------------------------------------
extern "C" void kernel_launch(void* const* d_in, const int* in_sizes, int n_in,
                              void* d_out, int out_size) {
    const float* x  = (const float*)d_in[0];
    const int*   ei = (const int*)d_in[1];
    const float* W1 = (const float*)d_in[2];
    const float* b1 = (const float*)d_in[3];
    const float* W2 = (const float*)d_in[4];
    const float* b2 = (const float*)d_in[5];
    float* out = (float*)d_out;

    const int N = in_sizes[0] / 128;
    const int E = in_sizes[1] / 2;
    const int* src = ei;
    const int* dst = ei + E;

    k_deg_init<<<(N + 255) / 256, 256>>>(N);
    k_deg_acc<<<(E + 255) / 256, 256>>>(dst, E);
    k_dinv<<<(N + 255) / 256, 256>>>(N);

    k_gemm1<<<(N + 63) / 64, 256>>>(x, W1, N);

    {
        long long T = (long long)E * 32;
        k_edge1<<<(int)((T + 255) / 256), 256>>>(src, dst, E);
    }

    k_gemm2<<<(N + 63) / 64, 256>>>(W2, b1, out, N);

    {
        long long T = (long long)E * 16;
        k_edge2<<<(int)((T + 255) / 256), 256>>>(src, dst, out, E);
    }

    {
        long long T = (long long)N * 16;
        k_final<<<(int)((T + 255) / 256), 256>>>(out, b2, N);
    }
}